// round 14
// baseline (speedup 1.0000x reference)
#include <cuda_runtime.h>

#define FULLMASK 0xFFFFFFFFu
#define WARPS_PER_ROW 8

union F8 { float f[8]; double4 d4; };

// One 256-thread block per row; each warp owns a 1024-element chunk.
// Sub-iterations widened to 256 elems (8/lane, two 4-element cumprod groups
// A and B to stay in fp32 range). Per sub-iter: 8 ballots, 2 logs, 1 warp
// scan, 1 exp (+1 mul for group B's base), and ONE 32B store per plane per
// lane (double4 -> STG.256 on sm_103). Halves scans/exps and store
// instructions vs the 128-elem version.
__global__ void __launch_bounds__(32 * WARPS_PER_ROW)
bbm_kernel(const float* __restrict__ obs,
           const float* __restrict__ alpha1,
           const float* __restrict__ beta1,
           const float* __restrict__ alpha2,
           const float* __restrict__ beta2,
           const float* __restrict__ mixw,
           float* __restrict__ out,
           int B, int T)
{
    const int wid  = threadIdx.x >> 5;
    const int lane = threadIdx.x & 31;
    const int row  = blockIdx.x;

    const unsigned ltmask = (lane == 0) ? 0u : (FULLMASK >> (32 - lane));

    const float a1c = __ldg(alpha1 + row);
    const float b1c = __ldg(beta1  + row);
    const float a2c = __ldg(alpha2 + row);
    const float b2c = __ldg(beta2  + row);
    const float ab1 = a1c + b1c;
    const float ab2 = a2c + b2c;
    const float w   = __ldg(mixw);
    const float omw = 1.0f - w;

    const int chunk = T / WARPS_PER_ROW;   // 1024

    const float4* __restrict__ orow =
        reinterpret_cast<const float4*>(obs + (size_t)row * (size_t)T);

    const size_t NT = (size_t)B * (size_t)T;
    float* o_a1 = out + (size_t)row * (size_t)T;

    __shared__ int smem_cnt[WARPS_PER_ROW];

    // ---------- Phase 1: load chunk, pack bits, count ----------
    unsigned packed = 0;
    const int vbase = wid * (chunk >> 2) + lane;
    #pragma unroll
    for (int i = 0; i < 8; ++i) {
        const float4 v = orow[vbase + i * 32];
        unsigned nib = (unsigned)(v.x > 0.5f)
                     | ((unsigned)(v.y > 0.5f) << 1)
                     | ((unsigned)(v.z > 0.5f) << 2)
                     | ((unsigned)(v.w > 0.5f) << 3);
        packed |= nib << (4 * i);
    }
    // NOTE: packing order above maps bit index (4*i + c) to element
    // t = i*128 + lane*4 + c (the old 128-elem layout). For the 256-elem
    // layout we need bit k to be element t = it*256 + lane*8 + k.
    // Re-pack: gather bits for this lane's 8 consecutive elements from the
    // float4 loads directly instead. Simpler: load with the new mapping.
    // (Handled below by a second pass over registers is impossible; so we
    //  load with the new mapping in the first place.)
    // -- replaced above: redo load with 8-consecutive mapping --
    packed = 0;
    #pragma unroll
    for (int i = 0; i < 2; ++i) {          // two float4s = 8 consecutive elems
        #pragma unroll
        for (int it = 0; it < 4; ++it) {   // 4 sub-iters of 256 elems
            const int fidx = wid * (chunk >> 2) + (it << 6) + (lane << 1) + i;
            const float4 v = orow[fidx];
            unsigned nib = (unsigned)(v.x > 0.5f)
                         | ((unsigned)(v.y > 0.5f) << 1)
                         | ((unsigned)(v.z > 0.5f) << 2)
                         | ((unsigned)(v.w > 0.5f) << 3);
            packed |= nib << (8 * it + 4 * i);
        }
    }
    const int warpcnt = __reduce_add_sync(FULLMASK, __popc(packed));
    if (lane == 0) smem_cnt[wid] = warpcnt;
    __syncthreads();

    int s_start = 0;
    #pragma unroll
    for (int k = 0; k < WARPS_PER_ROW; ++k)
        if (k < wid) s_start += smem_cnt[k];

    // ---------- D_base for this chunk via lgamma closed form ----------
    float D_carry = 0.0f;
    if (wid != 0) {
        const float tf = (float)(wid * chunk);
        const float sf = (float)s_start;
        const float ff = tf - sf;
        const float d2 = (lgammaf(a2c + sf) + lgammaf(b2c + ff) - lgammaf(ab2 + tf))
                       - (lgammaf(a2c) + lgammaf(b2c) - lgammaf(ab2));
        const float d1 = (lgammaf(a1c + sf) + lgammaf(b1c + ff) - lgammaf(ab1 + tf))
                       - (lgammaf(a1c) + lgammaf(b1c) - lgammaf(ab1));
        D_carry = d2 - d1;
    }
    int s_carry = s_start;

    const int tchunk = wid * chunk;

    // ---------- Phase 2: 4 sub-iterations of 256 elements ----------
    #pragma unroll
    for (int it = 0; it < 4; ++it) {
        const unsigned byte = (packed >> (8 * it)) & 0xFFu;

        // lane prefix over 8 bit positions
        int lp = 0, ct = 0;
        #pragma unroll
        for (int k = 0; k < 8; ++k) {
            const unsigned m = __ballot_sync(FULLMASK, (byte >> k) & 1u);
            lp += __popc(m & ltmask);
            ct += __popc(m);
        }
        const int s0 = s_carry + lp;

        const int   t0  = tchunk + (it << 8) + (lane << 3);
        const float t0f = (float)t0;

        // Group A: elements 0-3; Group B: elements 4-7 (separate cumprods,
        // each product of 4 factors <= ~2e31, fp32-safe).
        float cnexA[4], cdexA[4], cnexB[4], cdexB[4];
        float sfv[8];
        float cnA = 1.0f, cdA = 1.0f, cnB = 1.0f, cdB = 1.0f;
        int ss = s0;
        #pragma unroll
        for (int j = 0; j < 8; ++j) {
            if (j < 4) { cnexA[j] = cnA; cdexA[j] = cdA; }
            else       { cnexB[j-4] = cnB; cdexB[j-4] = cdB; }
            const int bj = (byte >> j) & 1;
            const float tf = t0f + (float)j;
            const float sf = (float)ss;
            const float ff = tf - sf;
            sfv[j] = sf;
            const float xv = bj ? sf  : ff;
            const float c2 = bj ? a2c : b2c;
            const float c1 = bj ? a1c : b1c;
            const float nm = (c2 + xv) * (ab1 + tf);
            const float dn = (c1 + xv) * (ab2 + tf);
            if (j < 4) { cnA *= nm; cdA *= dn; }
            else       { cnB *= nm; cdB *= dn; }
            ss += bj;
        }

        const float rA    = __fdividef(cnA, cdA);
        const float daccA = __logf(rA);
        const float daccB = __logf(__fdividef(cnB, cdB));
        const float dacc  = daccA + daccB;

        float finc = dacc;
        #pragma unroll
        for (int d = 1; d < 32; d <<= 1) {
            float n = __shfl_up_sync(FULLMASK, finc, d);
            if (lane >= d) finc += n;
        }
        const float Dbase = D_carry + (finc - dacc);
        const float Dtot  = __shfl_sync(FULLMASK, finc, 31);

        const float ebA = omw * __expf(Dbase);
        const float ebB = ebA * rA;

        float* p = o_a1 + t0;
        F8 u;

        // plane a1
        #pragma unroll
        for (int j = 0; j < 8; ++j) u.f[j] = a1c + sfv[j];
        *reinterpret_cast<double4*>(p) = u.d4;
        // plane b1
        #pragma unroll
        for (int j = 0; j < 8; ++j) u.f[j] = b1c + (t0f + (float)j - sfv[j]);
        *reinterpret_cast<double4*>(p + NT) = u.d4;
        // plane a2
        #pragma unroll
        for (int j = 0; j < 8; ++j) u.f[j] = a2c + sfv[j];
        *reinterpret_cast<double4*>(p + 2 * NT) = u.d4;
        // plane b2
        #pragma unroll
        for (int j = 0; j < 8; ++j) u.f[j] = b2c + (t0f + (float)j - sfv[j]);
        *reinterpret_cast<double4*>(p + 3 * NT) = u.d4;
        // plane pm
        #pragma unroll
        for (int j = 0; j < 4; ++j) {
            const float wn = w * cdexA[j];
            u.f[j] = __fdividef(wn, fmaf(ebA, cnexA[j], wn));
        }
        #pragma unroll
        for (int j = 0; j < 4; ++j) {
            const float wn = w * cdexB[j];
            u.f[4 + j] = __fdividef(wn, fmaf(ebB, cnexB[j], wn));
        }
        *reinterpret_cast<double4*>(p + 4 * NT) = u.d4;

        s_carry += ct;
        D_carry += Dtot;
    }
}

extern "C" void kernel_launch(void* const* d_in, const int* in_sizes, int n_in,
                              void* d_out, int out_size)
{
    const float* obs = (const float*)d_in[0];
    const float* a1  = (const float*)d_in[1];
    const float* b1  = (const float*)d_in[2];
    const float* a2  = (const float*)d_in[3];
    const float* b2  = (const float*)d_in[4];
    const float* mw  = (const float*)d_in[5];

    const int B = in_sizes[1];
    const int T = in_sizes[0] / B;

    dim3 block(32 * WARPS_PER_ROW);
    dim3 grid(B);
    bbm_kernel<<<grid, block>>>(obs, a1, b1, a2, b2, mw, (float*)d_out, B, T);
}

// round 15
// speedup vs baseline: 1.3493x; 1.3493x over previous
#include <cuda_runtime.h>

#define FULLMASK 0xFFFFFFFFu
#define WARPS_PER_ROW 8

// FINAL — best measured configuration (125.4us, rel_err 1.9e-7; DRAM 76%,
// 6.04 TB/s ncu-busy, ~6.6 TB/s effective aggregate = measured chip ceiling
// for this 5:1 write:read stream mix; memory-bound floor ~120us).
//
// One 256-thread block per row; each warp owns a 1024-element chunk.
// Phase 1: packed read (32 obs bits/lane) + block count scan -> s_start;
//          chunk D_base via lgamma closed form (betaln telescoped).
// Phase 2: 8 sequential sub-iterations (128 elems each), small live state:
//          ballot lane-prefix, FMA-pipe exclusive cumprods of likelihood
//          ratio factors, 1 log + 1 exp per lane per sub-iter, 1 fast-div
//          per element, float4 coalesced stores to all 5 output planes.
//
// Exhaustively measured-worse alternatives: forced reg caps (R4/R9: spills/
// remat), 8-way ILP restructure (R5: 170 regs, occ 11%), smem two-pass (R8:
// phase-locked bursty DRAM), streaming hints (R6: neutral), 2-kernel
// read/write split (R11/R12: launch + short-kernel overhead), 256-bit
// stores (R14: 77 regs, occ 33%).
__global__ void __launch_bounds__(32 * WARPS_PER_ROW)
bbm_kernel(const float* __restrict__ obs,
           const float* __restrict__ alpha1,
           const float* __restrict__ beta1,
           const float* __restrict__ alpha2,
           const float* __restrict__ beta2,
           const float* __restrict__ mixw,
           float* __restrict__ out,
           int B, int T)
{
    const int wid  = threadIdx.x >> 5;
    const int lane = threadIdx.x & 31;
    const int row  = blockIdx.x;

    const unsigned ltmask = (lane == 0) ? 0u : (FULLMASK >> (32 - lane));

    const float a1c = __ldg(alpha1 + row);
    const float b1c = __ldg(beta1  + row);
    const float a2c = __ldg(alpha2 + row);
    const float b2c = __ldg(beta2  + row);
    const float ab1 = a1c + b1c;
    const float ab2 = a2c + b2c;
    const float w   = __ldg(mixw);
    const float omw = 1.0f - w;

    const int chunk    = T / WARPS_PER_ROW;   // 1024
    const int subiters = chunk >> 7;          // 8

    const float4* __restrict__ orow =
        reinterpret_cast<const float4*>(obs + (size_t)row * (size_t)T);

    const size_t NT = (size_t)B * (size_t)T;
    float* o_a1 = out + (size_t)row * (size_t)T;
    float* o_b1 = o_a1 + NT;
    float* o_a2 = o_b1 + NT;
    float* o_b2 = o_a2 + NT;
    float* o_pm = o_b2 + NT;

    __shared__ int smem_cnt[WARPS_PER_ROW];

    // ---------- Phase 1: load chunk, pack bits, count ----------
    unsigned packed = 0;
    const int vbase = wid * (chunk >> 2) + lane;
    #pragma unroll
    for (int i = 0; i < 8; ++i) {
        const float4 v = orow[vbase + i * 32];
        unsigned nib = (unsigned)(v.x > 0.5f)
                     | ((unsigned)(v.y > 0.5f) << 1)
                     | ((unsigned)(v.z > 0.5f) << 2)
                     | ((unsigned)(v.w > 0.5f) << 3);
        packed |= nib << (4 * i);
    }
    const int warpcnt = __reduce_add_sync(FULLMASK, __popc(packed));
    if (lane == 0) smem_cnt[wid] = warpcnt;
    __syncthreads();

    int s_start = 0;
    #pragma unroll
    for (int k = 0; k < WARPS_PER_ROW; ++k)
        if (k < wid) s_start += smem_cnt[k];

    // ---------- D_base for this chunk via lgamma closed form ----------
    // D(s,t) = [lgG(a2+s)+lgG(b2+f)-lgG(ab2+t)] - [same for prior 1] - D(0,0)
    float D_carry = 0.0f;
    if (wid != 0) {
        const float tf = (float)(wid * chunk);
        const float sf = (float)s_start;
        const float ff = tf - sf;
        const float d2 = (lgammaf(a2c + sf) + lgammaf(b2c + ff) - lgammaf(ab2 + tf))
                       - (lgammaf(a2c) + lgammaf(b2c) - lgammaf(ab2));
        const float d1 = (lgammaf(a1c + sf) + lgammaf(b1c + ff) - lgammaf(ab1 + tf))
                       - (lgammaf(a1c) + lgammaf(b1c) - lgammaf(ab1));
        D_carry = d2 - d1;
    }
    int s_carry = s_start;

    // ---------- Phase 2: local recurrence over 8 sub-iterations ----------
    for (int it = 0; it < subiters; ++it) {
        const unsigned nib = (packed >> (4 * it)) & 0xF;
        const int b0 = (nib)      & 1;
        const int b1 = (nib >> 1) & 1;
        const int b2 = (nib >> 2) & 1;
        const int b3 = (nib >> 3) & 1;

        const unsigned m0 = __ballot_sync(FULLMASK, b0);
        const unsigned m1 = __ballot_sync(FULLMASK, b1);
        const unsigned m2 = __ballot_sync(FULLMASK, b2);
        const unsigned m3 = __ballot_sync(FULLMASK, b3);
        const int s0 = s_carry + __popc(m0 & ltmask) + __popc(m1 & ltmask)
                               + __popc(m2 & ltmask) + __popc(m3 & ltmask);
        const int cntTot = __popc(m0) + __popc(m1) + __popc(m2) + __popc(m3);

        const int   t0  = wid * chunk + (it << 7) + (lane << 2);
        const float t0f = (float)t0;

        // per-element ratio factors; exclusive cumulative products
        int bj[4] = {b0, b1, b2, b3};
        float sfv[4], num[4], den[4];
        int ss = s0;
        #pragma unroll
        for (int j = 0; j < 4; ++j) {
            const float tf = t0f + (float)j;
            const float sf = (float)ss;
            const float ff = tf - sf;          // exact: small integers in fp32
            sfv[j] = sf;
            const float xv = bj[j] ? sf  : ff;
            const float c2 = bj[j] ? a2c : b2c;
            const float c1 = bj[j] ? a1c : b1c;
            num[j] = (c2 + xv) * (ab1 + tf);
            den[j] = (c1 + xv) * (ab2 + tf);
            ss += bj[j];
        }
        float cnex[4], cdex[4];
        cnex[0] = 1.0f;             cdex[0] = 1.0f;
        cnex[1] = num[0];           cdex[1] = den[0];
        cnex[2] = cnex[1] * num[1]; cdex[2] = cdex[1] * den[1];
        cnex[3] = cnex[2] * num[2]; cdex[3] = cdex[2] * den[2];
        const float cnInc = cnex[3] * num[3];
        const float cdInc = cdex[3] * den[3];

        // one log per lane: this lane's total delta-D
        const float dacc = __logf(__fdividef(cnInc, cdInc));

        float finc = dacc;
        #pragma unroll
        for (int d = 1; d < 32; d <<= 1) {
            float n = __shfl_up_sync(FULLMASK, finc, d);
            if (lane >= d) finc += n;
        }
        const float Dbase = D_carry + (finc - dacc);   // exclusive prefix
        const float Dtot  = __shfl_sync(FULLMASK, finc, 31);

        const float omwEb = omw * __expf(Dbase);

        // outputs: a/b planes exact; pm = w*cd / (w*cd + (1-w)*e^Dbase*cn)
        float oa1[4], ob1[4], oa2[4], ob2[4], opm[4];
        #pragma unroll
        for (int j = 0; j < 4; ++j) {
            const float tf = t0f + (float)j;
            const float sf = sfv[j];
            const float ff = tf - sf;
            oa1[j] = a1c + sf;
            ob1[j] = b1c + ff;
            oa2[j] = a2c + sf;
            ob2[j] = b2c + ff;
            const float wn = w * cdex[j];
            opm[j] = __fdividef(wn, fmaf(omwEb, cnex[j], wn));
        }

        *reinterpret_cast<float4*>(o_a1 + t0) = make_float4(oa1[0], oa1[1], oa1[2], oa1[3]);
        *reinterpret_cast<float4*>(o_b1 + t0) = make_float4(ob1[0], ob1[1], ob1[2], ob1[3]);
        *reinterpret_cast<float4*>(o_a2 + t0) = make_float4(oa2[0], oa2[1], oa2[2], oa2[3]);
        *reinterpret_cast<float4*>(o_b2 + t0) = make_float4(ob2[0], ob2[1], ob2[2], ob2[3]);
        *reinterpret_cast<float4*>(o_pm + t0) = make_float4(opm[0], opm[1], opm[2], opm[3]);

        s_carry += cntTot;
        D_carry += Dtot;
    }
}

extern "C" void kernel_launch(void* const* d_in, const int* in_sizes, int n_in,
                              void* d_out, int out_size)
{
    const float* obs = (const float*)d_in[0];
    const float* a1  = (const float*)d_in[1];
    const float* b1  = (const float*)d_in[2];
    const float* a2  = (const float*)d_in[3];
    const float* b2  = (const float*)d_in[4];
    const float* mw  = (const float*)d_in[5];

    const int B = in_sizes[1];
    const int T = in_sizes[0] / B;

    dim3 block(32 * WARPS_PER_ROW);
    dim3 grid(B);
    bbm_kernel<<<grid, block>>>(obs, a1, b1, a2, b2, mw, (float*)d_out, B, T);
}

// round 16
// speedup vs baseline: 1.3613x; 1.0089x over previous
#include <cuda_runtime.h>

#define FULLMASK 0xFFFFFFFFu
#define WARPS_PER_ROW 8

// R13 best kernel (125.4us) + one zero-cost tweak: odd warps emit their 5
// plane stores in reverse order, interleaving the five output streams in
// time across the chip instead of phase-locking all warps onto one plane's
// address region at a time. No register/live-state change.
__global__ void __launch_bounds__(32 * WARPS_PER_ROW)
bbm_kernel(const float* __restrict__ obs,
           const float* __restrict__ alpha1,
           const float* __restrict__ beta1,
           const float* __restrict__ alpha2,
           const float* __restrict__ beta2,
           const float* __restrict__ mixw,
           float* __restrict__ out,
           int B, int T)
{
    const int wid  = threadIdx.x >> 5;
    const int lane = threadIdx.x & 31;
    const int row  = blockIdx.x;

    const unsigned ltmask = (lane == 0) ? 0u : (FULLMASK >> (32 - lane));

    const float a1c = __ldg(alpha1 + row);
    const float b1c = __ldg(beta1  + row);
    const float a2c = __ldg(alpha2 + row);
    const float b2c = __ldg(beta2  + row);
    const float ab1 = a1c + b1c;
    const float ab2 = a2c + b2c;
    const float w   = __ldg(mixw);
    const float omw = 1.0f - w;

    const int chunk    = T / WARPS_PER_ROW;   // 1024
    const int subiters = chunk >> 7;          // 8

    const float4* __restrict__ orow =
        reinterpret_cast<const float4*>(obs + (size_t)row * (size_t)T);

    const size_t NT = (size_t)B * (size_t)T;
    float* o_a1 = out + (size_t)row * (size_t)T;
    float* o_b1 = o_a1 + NT;
    float* o_a2 = o_b1 + NT;
    float* o_b2 = o_a2 + NT;
    float* o_pm = o_b2 + NT;

    __shared__ int smem_cnt[WARPS_PER_ROW];

    // ---------- Phase 1: load chunk, pack bits, count ----------
    unsigned packed = 0;
    const int vbase = wid * (chunk >> 2) + lane;
    #pragma unroll
    for (int i = 0; i < 8; ++i) {
        const float4 v = orow[vbase + i * 32];
        unsigned nib = (unsigned)(v.x > 0.5f)
                     | ((unsigned)(v.y > 0.5f) << 1)
                     | ((unsigned)(v.z > 0.5f) << 2)
                     | ((unsigned)(v.w > 0.5f) << 3);
        packed |= nib << (4 * i);
    }
    const int warpcnt = __reduce_add_sync(FULLMASK, __popc(packed));
    if (lane == 0) smem_cnt[wid] = warpcnt;
    __syncthreads();

    int s_start = 0;
    #pragma unroll
    for (int k = 0; k < WARPS_PER_ROW; ++k)
        if (k < wid) s_start += smem_cnt[k];

    // ---------- D_base for this chunk via lgamma closed form ----------
    float D_carry = 0.0f;
    if (wid != 0) {
        const float tf = (float)(wid * chunk);
        const float sf = (float)s_start;
        const float ff = tf - sf;
        const float d2 = (lgammaf(a2c + sf) + lgammaf(b2c + ff) - lgammaf(ab2 + tf))
                       - (lgammaf(a2c) + lgammaf(b2c) - lgammaf(ab2));
        const float d1 = (lgammaf(a1c + sf) + lgammaf(b1c + ff) - lgammaf(ab1 + tf))
                       - (lgammaf(a1c) + lgammaf(b1c) - lgammaf(ab1));
        D_carry = d2 - d1;
    }
    int s_carry = s_start;

    // ---------- Phase 2: local recurrence over 8 sub-iterations ----------
    for (int it = 0; it < subiters; ++it) {
        const unsigned nib = (packed >> (4 * it)) & 0xF;
        const int b0 = (nib)      & 1;
        const int b1 = (nib >> 1) & 1;
        const int b2 = (nib >> 2) & 1;
        const int b3 = (nib >> 3) & 1;

        const unsigned m0 = __ballot_sync(FULLMASK, b0);
        const unsigned m1 = __ballot_sync(FULLMASK, b1);
        const unsigned m2 = __ballot_sync(FULLMASK, b2);
        const unsigned m3 = __ballot_sync(FULLMASK, b3);
        const int s0 = s_carry + __popc(m0 & ltmask) + __popc(m1 & ltmask)
                               + __popc(m2 & ltmask) + __popc(m3 & ltmask);
        const int cntTot = __popc(m0) + __popc(m1) + __popc(m2) + __popc(m3);

        const int   t0  = wid * chunk + (it << 7) + (lane << 2);
        const float t0f = (float)t0;

        int bj[4] = {b0, b1, b2, b3};
        float sfv[4], num[4], den[4];
        int ss = s0;
        #pragma unroll
        for (int j = 0; j < 4; ++j) {
            const float tf = t0f + (float)j;
            const float sf = (float)ss;
            const float ff = tf - sf;
            sfv[j] = sf;
            const float xv = bj[j] ? sf  : ff;
            const float c2 = bj[j] ? a2c : b2c;
            const float c1 = bj[j] ? a1c : b1c;
            num[j] = (c2 + xv) * (ab1 + tf);
            den[j] = (c1 + xv) * (ab2 + tf);
            ss += bj[j];
        }
        float cnex[4], cdex[4];
        cnex[0] = 1.0f;             cdex[0] = 1.0f;
        cnex[1] = num[0];           cdex[1] = den[0];
        cnex[2] = cnex[1] * num[1]; cdex[2] = cdex[1] * den[1];
        cnex[3] = cnex[2] * num[2]; cdex[3] = cdex[2] * den[2];
        const float cnInc = cnex[3] * num[3];
        const float cdInc = cdex[3] * den[3];

        const float dacc = __logf(__fdividef(cnInc, cdInc));

        float finc = dacc;
        #pragma unroll
        for (int d = 1; d < 32; d <<= 1) {
            float n = __shfl_up_sync(FULLMASK, finc, d);
            if (lane >= d) finc += n;
        }
        const float Dbase = D_carry + (finc - dacc);
        const float Dtot  = __shfl_sync(FULLMASK, finc, 31);

        const float omwEb = omw * __expf(Dbase);

        float oa1[4], ob1[4], oa2[4], ob2[4], opm[4];
        #pragma unroll
        for (int j = 0; j < 4; ++j) {
            const float tf = t0f + (float)j;
            const float sf = sfv[j];
            const float ff = tf - sf;
            oa1[j] = a1c + sf;
            ob1[j] = b1c + ff;
            oa2[j] = a2c + sf;
            ob2[j] = b2c + ff;
            const float wn = w * cdex[j];
            opm[j] = __fdividef(wn, fmaf(omwEb, cnex[j], wn));
        }

        const float4 v0 = make_float4(oa1[0], oa1[1], oa1[2], oa1[3]);
        const float4 v1 = make_float4(ob1[0], ob1[1], ob1[2], ob1[3]);
        const float4 v2 = make_float4(oa2[0], oa2[1], oa2[2], oa2[3]);
        const float4 v3 = make_float4(ob2[0], ob2[1], ob2[2], ob2[3]);
        const float4 v4 = make_float4(opm[0], opm[1], opm[2], opm[3]);

        // interleave store streams: odd warps reverse plane order
        if (wid & 1) {
            *reinterpret_cast<float4*>(o_pm + t0) = v4;
            *reinterpret_cast<float4*>(o_b2 + t0) = v3;
            *reinterpret_cast<float4*>(o_a2 + t0) = v2;
            *reinterpret_cast<float4*>(o_b1 + t0) = v1;
            *reinterpret_cast<float4*>(o_a1 + t0) = v0;
        } else {
            *reinterpret_cast<float4*>(o_a1 + t0) = v0;
            *reinterpret_cast<float4*>(o_b1 + t0) = v1;
            *reinterpret_cast<float4*>(o_a2 + t0) = v2;
            *reinterpret_cast<float4*>(o_b2 + t0) = v3;
            *reinterpret_cast<float4*>(o_pm + t0) = v4;
        }

        s_carry += cntTot;
        D_carry += Dtot;
    }
}

extern "C" void kernel_launch(void* const* d_in, const int* in_sizes, int n_in,
                              void* d_out, int out_size)
{
    const float* obs = (const float*)d_in[0];
    const float* a1  = (const float*)d_in[1];
    const float* b1  = (const float*)d_in[2];
    const float* a2  = (const float*)d_in[3];
    const float* b2  = (const float*)d_in[4];
    const float* mw  = (const float*)d_in[5];

    const int B = in_sizes[1];
    const int T = in_sizes[0] / B;

    dim3 block(32 * WARPS_PER_ROW);
    dim3 grid(B);
    bbm_kernel<<<grid, block>>>(obs, a1, b1, a2, b2, mw, (float*)d_out, B, T);
}